// round 15
// baseline (speedup 1.0000x reference)
#include <cuda_runtime.h>
#include <cuda_bf16.h>
#include <cstdint>
#include <math.h>

#if defined(__CUDA_ARCH_FEAT_SM103_ALL) || defined(__CUDA_ARCH_FEAT_SM100_ALL)
#define HAS_TC 1
#else
#define HAS_TC 0
#endif

#define D    512
#define NH   8
#define HD   64
#define NL   4
#define FFD  2048
#define NCL  10
#define BB   8
#define TT   1024
#define NTOK (BB*TT)   // 8192

#define DDm (D*D)       // 262144
#define DFm (D*FFD)     // 1048576

// weight scratch offsets (elements), transposed [N,K] bf16 hi/lo
#define OFF_QKV 0
#define OFF_WO  (12*DDm)
#define OFF_W1  (16*DDm)
#define OFF_W2  (OFF_W1 + 4*DFm)
#define OFF_HW  (OFF_W2 + 4*DFm)
#define OFF_A1  (OFF_HW + DDm)
#define OFF_A2  (OFF_A1 + DDm)
#define WT_TOTAL (OFF_A2 + DDm)

// ---------------- scratch (device globals; no allocation) ----------------
__device__ __align__(16) float g_x [NTOK*D];
__device__ __align__(16) float g_h [NTOK*D];
__device__ __align__(16) __nv_bfloat16 g_hh  [NTOK*D],    g_hl  [NTOK*D];
__device__ __align__(16) __nv_bfloat16 g_qkvh[NTOK*3*D],  g_qkvl[NTOK*3*D];
__device__ __align__(16) __nv_bfloat16 g_vth [NTOK*D],    g_vtl [NTOK*D];
__device__ __align__(16) __nv_bfloat16 g_oh  [NTOK*D],    g_ol  [NTOK*D];
__device__ __align__(16) __nv_bfloat16 g_ffh [NTOK*FFD],  g_ffl [NTOK*FFD];
__device__ __align__(16) __nv_bfloat16 g_t1h [NTOK*D],    g_t1l [NTOK*D];
__device__ __align__(16) __nv_bfloat16 g_t2h [NTOK*D],    g_t2l [NTOK*D];
__device__ __align__(16) __nv_bfloat16 g_xh  [NTOK*D],    g_xl  [NTOK*D];
__device__ __align__(16) __nv_bfloat16 g_wth [WT_TOTAL],  g_wtl [WT_TOTAL];
__device__ __align__(16) float g_bcat[NL*3*D];
__device__ __align__(16) float g_xm[BB*D];

// ===================== PTX helpers (sm_103a) =====================
__device__ __forceinline__ uint32_t smem_u32(const void* p) {
    uint32_t a;
    asm("{ .reg .u64 t; cvta.to.shared.u64 t, %1; cvt.u32.u64 %0, t; }" : "=r"(a) : "l"(p));
    return a;
}
__device__ __forceinline__ uint32_t elect_one() {
    uint32_t p;
    asm volatile("{\n\t.reg .pred p;\n\telect.sync _|p, 0xFFFFFFFF;\n\tselp.b32 %0, 1, 0, p;\n\t}" : "=r"(p));
    return p;
}
#define TCGEN05_ALLOC(sa, n) \
    asm volatile("tcgen05.alloc.cta_group::1.sync.aligned.shared::cta.b32 [%0], %1;" \
                 :: "r"((uint32_t)(sa)), "r"((uint32_t)(n)) : "memory")
#define TCGEN05_DEALLOC(t, n) \
    asm volatile("tcgen05.dealloc.cta_group::1.sync.aligned.b32 %0, %1;" :: "r"(t), "r"((uint32_t)(n)))
#define TCGEN05_RELINQ() \
    asm volatile("tcgen05.relinquish_alloc_permit.cta_group::1.sync.aligned;")
#define TCGEN05_COMMIT(mb) \
    asm volatile("tcgen05.commit.cta_group::1.mbarrier::arrive::one.shared::cluster.b64 [%0];" \
                 :: "r"((uint32_t)(mb)) : "memory")
#define TCGEN05_FENCE_BEFORE() asm volatile("tcgen05.fence::before_thread_sync;" ::: "memory")
#define TCGEN05_FENCE_AFTER()  asm volatile("tcgen05.fence::after_thread_sync;" ::: "memory")
#define TCGEN05_WAIT_LD()      asm volatile("tcgen05.wait::ld.sync.aligned;" ::: "memory")
#define FENCE_ASYNC_SHARED()   asm volatile("fence.proxy.async.shared::cta;" ::: "memory")
#define MBARRIER_INIT(mb, c) \
    asm volatile("mbarrier.init.shared.b64 [%0], %1;" :: "r"((uint32_t)(mb)), "r"((uint32_t)(c)) : "memory")
#define MBARRIER_INVAL(mb) \
    asm volatile("mbarrier.inval.shared.b64 [%0];" :: "r"((uint32_t)(mb)) : "memory")
#define MBARRIER_WAIT_PARITY(mb, par) do { \
    uint32_t _m = (uint32_t)(mb), _p = (uint32_t)(par), _d; \
    asm volatile("{\n\t.reg .pred p;\n\t" \
        "mbarrier.try_wait.parity.acquire.cta.shared::cta.b64 p, [%1], %2;\n\t" \
        "selp.b32 %0, 1, 0, p;\n\t}" : "=r"(_d) : "r"(_m), "r"(_p) : "memory"); \
    if (!_d) { \
        asm volatile("{\n\t.reg .pred P1;\n\t" \
            "WL_%=:\n\t" \
            "mbarrier.try_wait.parity.acquire.cta.shared::cta.b64 P1, [%0], %1, 0x989680;\n\t" \
            "@P1 bra.uni WD_%=;\n\t" \
            "bra.uni WL_%=;\n\t" \
            "WD_%=:\n\t}" :: "r"(_m), "r"(_p) : "memory"); \
    } \
} while(0)
#define TCGEN05_LD_X32(r, ta) \
    asm volatile("tcgen05.ld.sync.aligned.32x32b.x32.b32 " \
        "{%0, %1, %2, %3, %4, %5, %6, %7, %8, %9, %10, %11, %12, %13, %14, %15, " \
        " %16, %17, %18, %19, %20, %21, %22, %23, %24, %25, %26, %27, %28, %29, %30, %31}, [%32];" \
        : "=r"((r)[0]),  "=r"((r)[1]),  "=r"((r)[2]),  "=r"((r)[3]), \
          "=r"((r)[4]),  "=r"((r)[5]),  "=r"((r)[6]),  "=r"((r)[7]), \
          "=r"((r)[8]),  "=r"((r)[9]),  "=r"((r)[10]), "=r"((r)[11]), \
          "=r"((r)[12]), "=r"((r)[13]), "=r"((r)[14]), "=r"((r)[15]), \
          "=r"((r)[16]), "=r"((r)[17]), "=r"((r)[18]), "=r"((r)[19]), \
          "=r"((r)[20]), "=r"((r)[21]), "=r"((r)[22]), "=r"((r)[23]), \
          "=r"((r)[24]), "=r"((r)[25]), "=r"((r)[26]), "=r"((r)[27]), \
          "=r"((r)[28]), "=r"((r)[29]), "=r"((r)[30]), "=r"((r)[31]) \
        : "r"(ta))
#define CP_ASYNC16(dst, src) \
    asm volatile("cp.async.cg.shared.global [%0], [%1], 16;" \
                 :: "r"((uint32_t)(dst)), "l"(src) : "memory")
#define CP_ASYNC_COMMIT() asm volatile("cp.async.commit_group;" ::: "memory")
#define CP_ASYNC_WAIT0()  asm volatile("cp.async.wait_group 0;" ::: "memory")

static constexpr uint64_t SMEM_DESC_BASE_SW128 =
    (uint64_t(2)  << 61) | (uint64_t(1) << 46) | (uint64_t(64) << 32) | (uint64_t(1) << 16);
#define MAKE_SMEM_DESC(a) (SMEM_DESC_BASE_SW128 | ((uint64_t)((a) >> 4) & 0x3FFF))

__device__ __forceinline__ void mma_bf16_ss(uint32_t d, uint64_t ad, uint64_t bd,
                                            uint32_t idesc, uint32_t en) {
#if HAS_TC
    uint32_t z = 0;
    asm volatile("{\n\t.reg .pred p;\n\tsetp.ne.u32 p, %5, 0;\n\t"
        "tcgen05.mma.cta_group::1.kind::f16 [%0], %1, %2, %3, {%4, %4, %4, %4}, p;\n\t}"
        :: "r"(d), "l"(ad), "l"(bd), "r"(idesc), "r"(z), "r"(en) : "memory");
#endif
}

// idesc: F32 accum, BF16 a/b; M=128 with N=128 / N=64
#define IDESC_128 ((1u<<4) | (1u<<7) | (1u<<10) | (16u<<17) | (8u<<24))
#define IDESC_64  ((1u<<4) | (1u<<7) | (1u<<10) | (8u<<17)  | (8u<<24))

#define EPS 132
#define SWZ(o) ((o) ^ (((o) >> 3) & 0x70))

// ---------------- embedding + pos enc + bias concat ------------------------
__global__ void embed_kernel(const int* __restrict__ tokens,
                             const float* __restrict__ emb,
                             float* __restrict__ x,
                             const float* __restrict__ bq, const float* __restrict__ bk,
                             const float* __restrict__ bv, float* __restrict__ bcat) {
    int i  = blockIdx.x * 256 + threadIdx.x;
    if (i < NL * 3 * D) {
        int l = i / (3 * D), c = i % (3 * D);
        int s = c >> 9, cc = c & 511;
        const float* src = (s == 0) ? bq : (s == 1) ? bk : bv;
        bcat[i] = src[l * D + cc];
    }
    int d  = i & (D - 1);
    int bt = i >> 9;
    int t  = bt & (TT - 1);
    int tok = tokens[bt];
    int kk = d >> 1;
    float freq = expf((float)(2 * kk) * (-0.0179889460f));
    float ang  = (float)t * freq;
    float pe   = (d & 1) ? cosf(ang) : sinf(ang);
    x[i] = emb[(size_t)tok * D + d] + pe;
}

// ---------------- layernorm ------------------------------------------------
__global__ __launch_bounds__(256) void ln_kernel(const float* __restrict__ x,
                                                 const float* __restrict__ g,
                                                 const float* __restrict__ b,
                                                 float* __restrict__ outf,
                                                 __nv_bfloat16* __restrict__ oh,
                                                 __nv_bfloat16* __restrict__ ol) {
    int warp = threadIdx.x >> 5, lane = threadIdx.x & 31;
    int row  = blockIdx.x * 8 + warp;
    const float* xr = x + (size_t)row * D;
    float v[16];
    float s = 0.f;
#pragma unroll
    for (int i = 0; i < 16; i++) { v[i] = xr[lane + i * 32]; s += v[i]; }
#pragma unroll
    for (int o = 16; o; o >>= 1) s += __shfl_xor_sync(0xffffffffu, s, o);
    float mean = s * (1.0f / D);
    float s2 = 0.f;
#pragma unroll
    for (int i = 0; i < 16; i++) { float dd = v[i] - mean; s2 += dd * dd; }
#pragma unroll
    for (int o = 16; o; o >>= 1) s2 += __shfl_xor_sync(0xffffffffu, s2, o);
    float rstd = rsqrtf(s2 * (1.0f / D) + 1e-5f);
#pragma unroll
    for (int i = 0; i < 16; i++) {
        int c = lane + i * 32;
        float y = (v[i] - mean) * rstd * g[c] + b[c];
        size_t idx = (size_t)row * D + c;
        if (outf) outf[idx] = y;
        else {
            __nv_bfloat16 hv = __float2bfloat16_rn(y);
            oh[idx] = hv;
            ol[idx] = __float2bfloat16_rn(y - __bfloat162float(hv));
        }
    }
}

// ---------------- generic weight transpose+split body ----------------------
__device__ __forceinline__ void wsplit_body(const float* W, __nv_bfloat16* th,
                                            __nv_bfloat16* tl, int K, int N,
                                            int k0, int n0, float tbuf[32][33]) {
    int x = threadIdx.x, y = threadIdx.y;
#pragma unroll
    for (int j = 0; j < 32; j += 8)
        tbuf[y + j][x] = W[(size_t)(k0 + y + j) * N + n0 + x];
    __syncthreads();
#pragma unroll
    for (int j = 0; j < 32; j += 8) {
        float v = tbuf[x][y + j];
        __nv_bfloat16 hv = __float2bfloat16_rn(v);
        size_t o = (size_t)(n0 + y + j) * K + k0 + x;
        th[o] = hv;
        tl[o] = __float2bfloat16_rn(v - __bfloat162float(hv));
    }
}

__global__ void wsplit_kernel(const float* __restrict__ W,
                              __nv_bfloat16* __restrict__ th,
                              __nv_bfloat16* __restrict__ tl,
                              int K, int N) {
    __shared__ float t[32][33];
    size_t mo = (size_t)blockIdx.z * K * N;
    wsplit_body(W + mo, th + mo, tl + mo, K, N,
                blockIdx.y * 32, blockIdx.x * 32, t);
}

__global__ void wsplit_qkvoh(const float* __restrict__ Wq, const float* __restrict__ Wk,
                             const float* __restrict__ Wv, const float* __restrict__ Wo,
                             const float* __restrict__ hw, const float* __restrict__ a1,
                             const float* __restrict__ a2,
                             __nv_bfloat16* __restrict__ th, __nv_bfloat16* __restrict__ tl) {
    __shared__ float t[32][33];
    int z = blockIdx.z;
    const float* src;
    size_t dst;
    if (z < 16) {
        int s = z >> 2, l = z & 3;
        src = ((s == 0) ? Wq : (s == 1) ? Wk : (s == 2) ? Wv : Wo) + (size_t)l * DDm;
        dst = (s < 3) ? (size_t)OFF_QKV + (size_t)l * 3 * DDm + (size_t)s * DDm
                      : (size_t)OFF_WO + (size_t)l * DDm;
    } else {
        int s = z - 16;
        src = (s == 0) ? hw : (s == 1) ? a1 : a2;
        dst = (size_t)OFF_HW + (size_t)s * DDm;
    }
    wsplit_body(src, th + dst, tl + dst, D, D, blockIdx.y * 32, blockIdx.x * 32, t);
}

// ---------------- tcgen05 split-bf16 GEMM (2 CTAs/SM, round-14) ------------
#define GSMEM (1024 + 65536)
__global__ __launch_bounds__(256, 2) __cluster_dims__(1, 1, 1)
void tc_gemm(const __nv_bfloat16* __restrict__ Ahi, const __nv_bfloat16* __restrict__ Alo,
             const __nv_bfloat16* __restrict__ Bhi, const __nv_bfloat16* __restrict__ Blo,
             const float* __restrict__ bias, const float* __restrict__ res,
             float* __restrict__ Cf,
             __nv_bfloat16* __restrict__ Ch, __nv_bfloat16* __restrict__ Cl,
             int M, int N, int K, int act,
             __nv_bfloat16* __restrict__ Vth, __nv_bfloat16* __restrict__ Vtl) {
#if HAS_TC
    extern __shared__ char smem[];
    uint32_t sb = smem_u32(smem);
    int tid = threadIdx.x, wid = tid >> 5, lane = tid & 31;
    int bm = blockIdx.y * 128, bn = blockIdx.x * 128;

    if (wid == 0) { TCGEN05_ALLOC(sb, 128); TCGEN05_RELINQ(); }
    if (tid == 0) { MBARRIER_INIT(sb + 16, 1); }
    __syncthreads();
    uint32_t tmem;
    asm volatile("ld.shared.b32 %0, [%1];" : "=r"(tmem) : "r"(sb));

    int nchunk = K >> 6;
    int ph = 0;

    for (int c = 0; c < nchunk; c++) {
        if (c > 0) { MBARRIER_WAIT_PARITY(sb + 16, ph); ph ^= 1; }
#pragma unroll
        for (int t = 0; t < 4; t++) {
            const __nv_bfloat16* src = (t == 0) ? Ahi : (t == 1) ? Alo : (t == 2) ? Bhi : Blo;
            int rb = (t < 2) ? bm : bn;
            uint32_t tb = sb + 1024u + t * 16384u;
#pragma unroll
            for (int i = 0; i < 4; i++) {
                int e = tid + i * 256;
                int r = e >> 3, cq = e & 7;
                uint32_t off = (uint32_t)(r * 128 + cq * 16);
                CP_ASYNC16(tb + SWZ(off), src + (size_t)(rb + r) * K + c * 64 + cq * 8);
            }
        }
        CP_ASYNC_COMMIT();
        CP_ASYNC_WAIT0();
        FENCE_ASYNC_SHARED();
        __syncthreads();
        if (wid == 0) {
            if (elect_one()) {
                uint64_t aH = MAKE_SMEM_DESC(sb + 1024u);
                uint64_t aL = MAKE_SMEM_DESC(sb + 1024u + 16384u);
                uint64_t bH = MAKE_SMEM_DESC(sb + 1024u + 32768u);
                uint64_t bL = MAKE_SMEM_DESC(sb + 1024u + 49152u);
#pragma unroll
                for (int s = 0; s < 4; s++)
                    mma_bf16_ss(tmem, aH + 2 * s, bH + 2 * s, IDESC_128, (c != 0 || s != 0));
#pragma unroll
                for (int s = 0; s < 4; s++)
                    mma_bf16_ss(tmem, aH + 2 * s, bL + 2 * s, IDESC_128, 1u);
#pragma unroll
                for (int s = 0; s < 4; s++)
                    mma_bf16_ss(tmem, aL + 2 * s, bH + 2 * s, IDESC_128, 1u);
                TCGEN05_COMMIT(sb + 16);
            }
        }
    }
    MBARRIER_WAIT_PARITY(sb + 16, ph); ph ^= 1;
    TCGEN05_FENCE_AFTER();

    int w4 = wid & 3;
    int cb = (wid >> 2) * 64;
    uint32_t dr[64];
    TCGEN05_LD_X32(dr,      tmem + cb);
    TCGEN05_LD_X32(dr + 32, tmem + cb + 32);
    TCGEN05_WAIT_LD();
    TCGEN05_FENCE_BEFORE();
    float* so = (float*)(smem + 1024);
    bool dovt = (Vth != nullptr) && (bn >= 1024);
    int b  = bm >> 10;
    int t0 = bm & 1023;
    int vb = bn - 1024;
#pragma unroll
    for (int p = 0; p < 2; p++) {
        __syncthreads();
        if ((w4 >> 1) == p) {
            int rloc = (w4 & 1) * 32 + lane;
#pragma unroll
            for (int j = 0; j < 64; j++) so[rloc * EPS + cb + j] = __uint_as_float(dr[j]);
        }
        __syncthreads();
#pragma unroll
        for (int i = 0; i < 8; i++) {
            int e = tid + i * 256;
            int rl = e >> 5, c4 = (e & 31) << 2;
            float4 v = *(float4*)&so[rl * EPS + c4];
            float* vv = (float*)&v;
            int row = bm + p * 64 + rl;
            if (bias) {
                float4 bv = *(const float4*)&bias[bn + c4];
                vv[0] += bv.x; vv[1] += bv.y; vv[2] += bv.z; vv[3] += bv.w;
            }
            if (act == 1) {
#pragma unroll
                for (int q = 0; q < 4; q++)
                    vv[q] = 0.5f * vv[q] * (1.0f + erff(vv[q] * 0.70710678f));
            } else if (act == 2) {
#pragma unroll
                for (int q = 0; q < 4; q++) vv[q] = tanhf(vv[q]);
            }
            if (res) {
                float4 rv = *(const float4*)&res[(size_t)row * N + bn + c4];
                vv[0] += rv.x; vv[1] += rv.y; vv[2] += rv.z; vv[3] += rv.w;
            }
            size_t gidx = (size_t)row * N + bn + c4;
            if (Cf) *(float4*)&Cf[gidx] = v;
            if (Ch) {
                __nv_bfloat16 h0 = __float2bfloat16_rn(vv[0]);
                __nv_bfloat16 h1 = __float2bfloat16_rn(vv[1]);
                __nv_bfloat16 h2 = __float2bfloat16_rn(vv[2]);
                __nv_bfloat16 h3 = __float2bfloat16_rn(vv[3]);
                __nv_bfloat162 hp0(h0, h1), hp1(h2, h3);
                __nv_bfloat162 lp0(__float2bfloat16_rn(vv[0] - __bfloat162float(h0)),
                                   __float2bfloat16_rn(vv[1] - __bfloat162float(h1)));
                __nv_bfloat162 lp1(__float2bfloat16_rn(vv[2] - __bfloat162float(h2)),
                                   __float2bfloat16_rn(vv[3] - __bfloat162float(h3)));
                *(uint2*)&Ch[gidx] = make_uint2(*(uint32_t*)&hp0, *(uint32_t*)&hp1);
                *(uint2*)&Cl[gidx] = make_uint2(*(uint32_t*)&lp0, *(uint32_t*)&lp1);
            }
            if (dovt) *(float4*)&so[rl * EPS + c4] = v;
        }
        if (dovt) {
            __syncthreads();
#pragma unroll
            for (int i = 0; i < 8; i++) {
                int e = tid + i * 256;
                int cl = e >> 4, tg = (e & 15) << 2;
                float f0 = so[(tg + 0) * EPS + cl];
                float f1 = so[(tg + 1) * EPS + cl];
                float f2 = so[(tg + 2) * EPS + cl];
                float f3 = so[(tg + 3) * EPS + cl];
                __nv_bfloat16 h0 = __float2bfloat16_rn(f0);
                __nv_bfloat16 h1 = __float2bfloat16_rn(f1);
                __nv_bfloat16 h2 = __float2bfloat16_rn(f2);
                __nv_bfloat16 h3 = __float2bfloat16_rn(f3);
                __nv_bfloat162 hp0(h0, h1), hp1(h2, h3);
                __nv_bfloat162 lp0(__float2bfloat16_rn(f0 - __bfloat162float(h0)),
                                   __float2bfloat16_rn(f1 - __bfloat162float(h1)));
                __nv_bfloat162 lp1(__float2bfloat16_rn(f2 - __bfloat162float(h2)),
                                   __float2bfloat16_rn(f3 - __bfloat162float(h3)));
                size_t g = ((size_t)(b * 512 + vb + cl)) * 1024 + t0 + p * 64 + tg;
                *(uint2*)&Vth[g] = make_uint2(*(uint32_t*)&hp0, *(uint32_t*)&hp1);
                *(uint2*)&Vtl[g] = make_uint2(*(uint32_t*)&lp0, *(uint32_t*)&lp1);
            }
        }
    }
    __syncthreads();
    if (tid == 0) MBARRIER_INVAL(sb + 16);
    __syncthreads();
    if (wid == 0) TCGEN05_DEALLOC(tmem, 128);
#else
    // compile-only fallback for non-'a' PTX pass (never selected on GB300)
    extern __shared__ char smem[];
    float* As = (float*)smem;
    float* Bs = (float*)(smem + 4096);
    int tid = threadIdx.x;
    int bm = blockIdx.y * 128, bn = blockIdx.x * 128;
    int tx = tid & 15, ty = tid >> 4;
    int lr = tid >> 1, lk = (tid & 1) * 4;
    float acc[8][8];
#pragma unroll
    for (int i = 0; i < 8; i++)
#pragma unroll
        for (int j = 0; j < 8; j++) acc[i][j] = 0.f;
    for (int k0 = 0; k0 < K; k0 += 8) {
        float av[4], bv[4];
#pragma unroll
        for (int i = 0; i < 4; i++) {
            size_t ai = (size_t)(bm + lr) * K + k0 + lk + i;
            av[i] = __bfloat162float(Ahi[ai]) + __bfloat162float(Alo[ai]);
            size_t bi = (size_t)(bn + lr) * K + k0 + lk + i;
            bv[i] = __bfloat162float(Bhi[bi]) + __bfloat162float(Blo[bi]);
        }
        __syncthreads();
#pragma unroll
        for (int i = 0; i < 4; i++) {
            As[(lk + i) * 128 + lr] = av[i];
            Bs[(lk + i) * 128 + lr] = bv[i];
        }
        __syncthreads();
#pragma unroll
        for (int kk = 0; kk < 8; kk++) {
            float ar8[8], br8[8];
#pragma unroll
            for (int i = 0; i < 8; i++) { ar8[i] = As[kk * 128 + ty * 8 + i]; br8[i] = Bs[kk * 128 + tx * 8 + i]; }
#pragma unroll
            for (int i = 0; i < 8; i++)
#pragma unroll
                for (int j = 0; j < 8; j++) acc[i][j] += ar8[i] * br8[j];
        }
    }
#pragma unroll
    for (int i = 0; i < 8; i++) {
        int row = bm + ty * 8 + i;
#pragma unroll
        for (int j = 0; j < 8; j++) {
            int col = bn + tx * 8 + j;
            float v = acc[i][j];
            if (bias) v += bias[col];
            if (act == 1) v = 0.5f * v * (1.0f + erff(v * 0.70710678f));
            else if (act == 2) v = tanhf(v);
            if (res) v += res[(size_t)row * N + col];
            if (Cf) Cf[(size_t)row * N + col] = v;
            if (Ch) {
                __nv_bfloat16 hv = __float2bfloat16_rn(v);
                Ch[(size_t)row * N + col] = hv;
                Cl[(size_t)row * N + col] = __float2bfloat16_rn(v - __bfloat162float(hv));
            }
            if (Vth && bn >= 1024) {
                int b = row >> 10, t = row & 1023;
                size_t g = ((size_t)(b * 512 + (bn - 1024) + tx * 8 + j)) * 1024 + t;
                __nv_bfloat16 hv = __float2bfloat16_rn(v);
                Vth[g] = hv;
                Vtl[g] = __float2bfloat16_rn(v - __bfloat162float(hv));
            }
        }
    }
#endif
}

// ---------------- tcgen05 attention (64-key tiles, 2 CTAs/SM) --------------
// Per CTA: one (b,h), 128-query tile, 16 key-tiles of 64. S in TMEM (64 cols),
// O accumulated in TMEM (64 cols). p = exp(s/8) unnormalized. Occupancy 2
// (98 KB SMEM, 128 TMEM cols) provides the cross-chain overlap.
#define AQ_H 1024
#define AQ_L (AQ_H+16384)
#define AK_H (AQ_L+16384)
#define AK_L (AK_H+8192)
#define AV_H (AK_L+8192)
#define AV_L (AV_H+8192)
#define AP_H (AV_L+8192)
#define AP_L (AP_H+16384)
#define A_LS (AP_L+16384)
#define ATT_SMEM (A_LS+1024)   // 100,352 B

__global__ __launch_bounds__(256, 2) __cluster_dims__(1, 1, 1)
void tc_attn(const __nv_bfloat16* __restrict__ qkvh, const __nv_bfloat16* __restrict__ qkvl,
             const __nv_bfloat16* __restrict__ vth, const __nv_bfloat16* __restrict__ vtl,
             __nv_bfloat16* __restrict__ Oh, __nv_bfloat16* __restrict__ Ol) {
#if HAS_TC
    extern __shared__ char smem[];
    uint32_t sb = smem_u32(smem);
    int tid = threadIdx.x, wid = tid >> 5, lane = tid & 31;
    int bh = blockIdx.x, b = bh >> 3, h = bh & 7;
    int q0 = blockIdx.y * 128;
    int w4 = wid & 3, half = wid >> 2, cb = half * 32;
    int srow = w4 * 32 + lane;

    if (wid == 0) { TCGEN05_ALLOC(sb, 128); TCGEN05_RELINQ(); }
    if (tid == 0) { MBARRIER_INIT(sb + 16, 1); }
    __syncthreads();
    uint32_t tmem;
    asm volatile("ld.shared.b32 %0, [%1];" : "=r"(tmem) : "r"(sb));

    const __nv_bfloat16* Qh = qkvh + (size_t)(b * TT + q0) * 1536 + h * 64;
    const __nv_bfloat16* Ql = qkvl + (size_t)(b * TT + q0) * 1536 + h * 64;
    const __nv_bfloat16* Kh = qkvh + (size_t)(b * TT) * 1536 + 512 + h * 64;
    const __nv_bfloat16* Kl = qkvl + (size_t)(b * TT) * 1536 + 512 + h * 64;
    const __nv_bfloat16* Vh = vth + (size_t)bh * 64 * TT;
    const __nv_bfloat16* Vl = vtl + (size_t)bh * 64 * TT;

    // preload Q (stays resident)
#pragma unroll
    for (int i = 0; i < 4; i++) {
        int e = tid + i * 256;
        int r = e >> 3, u = e & 7;
        uint32_t off = SWZ((uint32_t)(r * 128 + u * 16));
        CP_ASYNC16(sb + AQ_H + off, Qh + (size_t)r * 1536 + u * 8);
        CP_ASYNC16(sb + AQ_L + off, Ql + (size_t)r * 1536 + u * 8);
    }
    CP_ASYNC_COMMIT();

    float lacc = 0.f;
    int ph = 0;

    for (int kt = 0; kt < 16; kt++) {
        if (kt > 0) { MBARRIER_WAIT_PARITY(sb + 16, ph); ph ^= 1; }  // PV(kt-1) done: bufs free
        // K tile (64 keys x 64 d) + V^T tile (64 hd x 64 keys), hi+lo
#pragma unroll
        for (int i = 0; i < 2; i++) {
            int e = tid + i * 256;
            int r = e >> 3, u = e & 7;
            uint32_t off = SWZ((uint32_t)(r * 128 + u * 16));
            CP_ASYNC16(sb + AK_H + off, Kh + (size_t)(kt * 64 + r) * 1536 + u * 8);
            CP_ASYNC16(sb + AK_L + off, Kl + (size_t)(kt * 64 + r) * 1536 + u * 8);
            CP_ASYNC16(sb + AV_H + off, Vh + (size_t)r * TT + kt * 64 + u * 8);
            CP_ASYNC16(sb + AV_L + off, Vl + (size_t)r * TT + kt * 64 + u * 8);
        }
        CP_ASYNC_COMMIT();
        CP_ASYNC_WAIT0();
        FENCE_ASYNC_SHARED();
        __syncthreads();
        if (wid == 0 && elect_one()) {
            uint64_t qH = MAKE_SMEM_DESC(sb + AQ_H), qL = MAKE_SMEM_DESC(sb + AQ_L);
            uint64_t kH = MAKE_SMEM_DESC(sb + AK_H), kL = MAKE_SMEM_DESC(sb + AK_L);
#pragma unroll
            for (int s = 0; s < 4; s++) mma_bf16_ss(tmem, qH + 2 * s, kH + 2 * s, IDESC_64, s != 0);
#pragma unroll
            for (int s = 0; s < 4; s++) mma_bf16_ss(tmem, qH + 2 * s, kL + 2 * s, IDESC_64, 1u);
#pragma unroll
            for (int s = 0; s < 4; s++) mma_bf16_ss(tmem, qL + 2 * s, kH + 2 * s, IDESC_64, 1u);
            TCGEN05_COMMIT(sb + 16);
        }
        MBARRIER_WAIT_PARITY(sb + 16, ph); ph ^= 1;   // QK(kt) done
        TCGEN05_FENCE_AFTER();
        uint32_t dr[32];
        TCGEN05_LD_X32(dr, tmem + cb);
        TCGEN05_WAIT_LD();
#pragma unroll
        for (int j = 0; j < 32; j += 2) {
            float p0 = __expf(__uint_as_float(dr[j])     * 0.125f);
            float p1 = __expf(__uint_as_float(dr[j + 1]) * 0.125f);
            lacc += p0 + p1;
            __nv_bfloat16 h0 = __float2bfloat16_rn(p0), h1 = __float2bfloat16_rn(p1);
            __nv_bfloat162 hp(h0, h1);
            __nv_bfloat162 lp(__float2bfloat16_rn(p0 - __bfloat162float(h0)),
                              __float2bfloat16_rn(p1 - __bfloat162float(h1)));
            uint32_t off = SWZ((uint32_t)(srow * 128 + (cb + j) * 2));
            *(uint32_t*)(smem + AP_H + off) = *(uint32_t*)&hp;
            *(uint32_t*)(smem + AP_L + off) = *(uint32_t*)&lp;
        }
        TCGEN05_FENCE_BEFORE();
        FENCE_ASYNC_SHARED();
        __syncthreads();
        if (wid == 0 && elect_one()) {
            uint64_t pH = MAKE_SMEM_DESC(sb + AP_H), pL = MAKE_SMEM_DESC(sb + AP_L);
            uint64_t vH = MAKE_SMEM_DESC(sb + AV_H), vL = MAKE_SMEM_DESC(sb + AV_L);
#pragma unroll
            for (int s = 0; s < 4; s++)
                mma_bf16_ss(tmem + 64, pH + 2 * s, vH + 2 * s, IDESC_64, !(kt == 0 && s == 0));
#pragma unroll
            for (int s = 0; s < 4; s++)
                mma_bf16_ss(tmem + 64, pH + 2 * s, vL + 2 * s, IDESC_64, 1u);
#pragma unroll
            for (int s = 0; s < 4; s++)
                mma_bf16_ss(tmem + 64, pL + 2 * s, vH + 2 * s, IDESC_64, 1u);
            TCGEN05_COMMIT(sb + 16);
        }
    }
    MBARRIER_WAIT_PARITY(sb + 16, ph); ph ^= 1;
    TCGEN05_FENCE_AFTER();

    // exchange row sums between column-halves
    *(float*)(smem + A_LS + (half * 128 + srow) * 4) = lacc;
    __syncthreads();
    if (wid < 4) {
        float lt = *(float*)(smem + A_LS + srow * 4) +
                   *(float*)(smem + A_LS + (128 + srow) * 4);
        float invl = 1.0f / lt;
        uint32_t orv[64];
        TCGEN05_LD_X32(orv,      tmem + 64);
        TCGEN05_LD_X32(orv + 32, tmem + 96);
        TCGEN05_WAIT_LD();
        TCGEN05_FENCE_BEFORE();
#pragma unroll
        for (int j = 0; j < 64; j += 2) {
            float o0 = __uint_as_float(orv[j]) * invl;
            float o1 = __uint_as_float(orv[j + 1]) * invl;
            __nv_bfloat16 h0 = __float2bfloat16_rn(o0), h1 = __float2bfloat16_rn(o1);
            __nv_bfloat162 hp(h0, h1);
            __nv_bfloat162 lp(__float2bfloat16_rn(o0 - __bfloat162float(h0)),
                              __float2bfloat16_rn(o1 - __bfloat162float(h1)));
            uint32_t off = SWZ((uint32_t)(srow * 128 + j * 2));
            *(uint32_t*)(smem + AP_H + off) = *(uint32_t*)&hp;
            *(uint32_t*)(smem + AP_L + off) = *(uint32_t*)&lp;
        }
    }
    __syncthreads();
#pragma unroll
    for (int i = 0; i < 4; i++) {
        int e = tid + i * 256;
        int r = e >> 3, u = e & 7;
        uint32_t off = SWZ((uint32_t)(r * 128 + u * 16));
        size_t g = (size_t)(b * TT + q0 + r) * D + h * 64 + u * 8;
        *(uint4*)(Oh + g) = *(uint4*)(smem + AP_H + off);
        *(uint4*)(Ol + g) = *(uint4*)(smem + AP_L + off);
    }
    __syncthreads();
    if (tid == 0) MBARRIER_INVAL(sb + 16);
    __syncthreads();
    if (wid == 0) TCGEN05_DEALLOC(tmem, 128);
#endif
}

// ---------------- mean over T (64 blocks, tree reduce) ---------------------
__global__ __launch_bounds__(256) void mean_kernel(const float* __restrict__ x,
                                                   float* __restrict__ out) {
    __shared__ float red[256];
    int b = blockIdx.x >> 3;
    int base = (blockIdx.x & 7) * 64;
    int dc = threadIdx.x & 63, tq = threadIdx.x >> 6;
    float s = 0.f;
    for (int t = tq; t < TT; t += 4)
        s += x[((size_t)(b * TT + t)) * D + base + dc];
    red[threadIdx.x] = s;
    __syncthreads();
    if (threadIdx.x < 64) {
        float tot = red[dc] + red[64 + dc] + red[128 + dc] + red[192 + dc];
        out[b * D + base + dc] = tot * (1.0f / TT);
    }
}

// ---------------- classifier ----------------------------------------------
__global__ void cls_kernel(const float* __restrict__ xm, const float* __restrict__ W,
                           const float* __restrict__ bias, float* __restrict__ out) {
    int i = threadIdx.x;
    if (i < BB * NCL) {
        int b = i / NCL, c = i % NCL;
        float s = bias[c];
        for (int d = 0; d < D; d++) s += xm[b * D + d] * W[d * NCL + c];
        out[i] = s;
    }
}

// ---------------- launch ---------------------------------------------------
extern "C" void kernel_launch(void* const* d_in, const int* in_sizes, int n_in,
                              void* d_out, int out_size) {
    const int*   tokens = (const int*)  d_in[0];
    const float* emb    = (const float*)d_in[1];
    const float* Wq = (const float*)d_in[2],  *bq = (const float*)d_in[3];
    const float* Wk = (const float*)d_in[4],  *bk = (const float*)d_in[5];
    const float* Wv = (const float*)d_in[6],  *bv = (const float*)d_in[7];
    const float* Wo = (const float*)d_in[8],  *bo = (const float*)d_in[9];
    const float* ln1g = (const float*)d_in[10], *ln1b = (const float*)d_in[11];
    const float* ln2g = (const float*)d_in[12], *ln2b = (const float*)d_in[13];
    const float* W1 = (const float*)d_in[14], *b1 = (const float*)d_in[15];
    const float* W2 = (const float*)d_in[16], *b2 = (const float*)d_in[17];
    const float* heavy_w  = (const float*)d_in[18];
    const float* heavy_b  = (const float*)d_in[19];
    const float* heavy_a1 = (const float*)d_in[20];
    const float* heavy_a2 = (const float*)d_in[21];
    const float* norm_g = (const float*)d_in[22], *norm_b = (const float*)d_in[23];
    const float* cls_W  = (const float*)d_in[24], *cls_b  = (const float*)d_in[25];

    float *x, *h, *xm, *bcat;
    __nv_bfloat16 *hh, *hl, *qkvh, *qkvl, *vth, *vtl, *oh, *ol,
                  *ffh, *ffl, *t1h, *t1l, *t2h, *t2l, *xh, *xl, *wth, *wtl;
    cudaGetSymbolAddress((void**)&x,    g_x);
    cudaGetSymbolAddress((void**)&h,    g_h);
    cudaGetSymbolAddress((void**)&hh,   g_hh);   cudaGetSymbolAddress((void**)&hl,   g_hl);
    cudaGetSymbolAddress((void**)&qkvh, g_qkvh); cudaGetSymbolAddress((void**)&qkvl, g_qkvl);
    cudaGetSymbolAddress((void**)&vth,  g_vth);  cudaGetSymbolAddress((void**)&vtl,  g_vtl);
    cudaGetSymbolAddress((void**)&oh,   g_oh);   cudaGetSymbolAddress((void**)&ol,   g_ol);
    cudaGetSymbolAddress((void**)&ffh,  g_ffh);  cudaGetSymbolAddress((void**)&ffl,  g_ffl);
    cudaGetSymbolAddress((void**)&t1h,  g_t1h);  cudaGetSymbolAddress((void**)&t1l,  g_t1l);
    cudaGetSymbolAddress((void**)&t2h,  g_t2h);  cudaGetSymbolAddress((void**)&t2l,  g_t2l);
    cudaGetSymbolAddress((void**)&xh,   g_xh);   cudaGetSymbolAddress((void**)&xl,   g_xl);
    cudaGetSymbolAddress((void**)&wth,  g_wth);  cudaGetSymbolAddress((void**)&wtl,  g_wtl);
    cudaGetSymbolAddress((void**)&bcat, g_bcat);
    cudaGetSymbolAddress((void**)&xm,   g_xm);

    cudaFuncSetAttribute(tc_gemm, cudaFuncAttributeMaxDynamicSharedMemorySize, GSMEM);
    cudaFuncSetAttribute(tc_attn, cudaFuncAttributeMaxDynamicSharedMemorySize, ATT_SMEM);

    embed_kernel<<<NTOK * D / 256, 256>>>(tokens, emb, x, bq, bk, bv, bcat);
    wsplit_kernel<<<dim3(FFD/32, D/32,   NL), dim3(32,8)>>>(W1, wth + OFF_W1, wtl + OFF_W1, D, FFD);
    wsplit_kernel<<<dim3(D/32,   FFD/32, NL), dim3(32,8)>>>(W2, wth + OFF_W2, wtl + OFF_W2, FFD, D);
    wsplit_qkvoh<<<dim3(D/32, D/32, 19), dim3(32,8)>>>(Wq, Wk, Wv, Wo,
                                                       heavy_w, heavy_a1, heavy_a2, wth, wtl);

    dim3 gD(D / 128,     NTOK / 128);   // N=512
    dim3 gQ(3*D / 128,   NTOK / 128);   // N=1536 fused QKV
    dim3 gF(FFD / 128,   NTOK / 128);   // N=2048

    for (int l = 0; l < NL; l++) {
        ln_kernel<<<NTOK / 8, 256>>>(x, ln1g + l * D, ln1b + l * D, nullptr, hh, hl);
        tc_gemm<<<gQ, 256, GSMEM>>>(hh, hl,
                                    wth + OFF_QKV + (size_t)l * 3 * DDm,
                                    wtl + OFF_QKV + (size_t)l * 3 * DDm,
                                    bcat + l * 3 * D, nullptr,
                                    nullptr, qkvh, qkvl, NTOK, 3 * D, D, 0,
                                    vth, vtl);
        tc_attn<<<dim3(BB * NH, TT / 128), 256, ATT_SMEM>>>(qkvh, qkvl, vth, vtl, oh, ol);
        tc_gemm<<<gD, 256, GSMEM>>>(oh, ol,
                                    wth + OFF_WO + (size_t)l * DDm,
                                    wtl + OFF_WO + (size_t)l * DDm,
                                    bo + l * D, x, x, nullptr, nullptr, NTOK, D, D, 0,
                                    nullptr, nullptr);
        ln_kernel<<<NTOK / 8, 256>>>(x, ln2g + l * D, ln2b + l * D, nullptr, hh, hl);
        tc_gemm<<<gF, 256, GSMEM>>>(hh, hl,
                                    wth + OFF_W1 + (size_t)l * DFm,
                                    wtl + OFF_W1 + (size_t)l * DFm,
                                    b1 + l * FFD, nullptr, nullptr, ffh, ffl, NTOK, FFD, D, 1,
                                    nullptr, nullptr);
        tc_gemm<<<gD, 256, GSMEM>>>(ffh, ffl,
                                    wth + OFF_W2 + (size_t)l * DFm,
                                    wtl + OFF_W2 + (size_t)l * DFm,
                                    b2 + l * D, x, x,
                                    (l == NL - 1) ? xh : nullptr,
                                    (l == NL - 1) ? xl : nullptr,
                                    NTOK, D, FFD, 0, nullptr, nullptr);
    }

    tc_gemm<<<gD, 256, GSMEM>>>(xh, xl, wth + OFF_HW, wtl + OFF_HW,
                                nullptr, nullptr, nullptr, t1h, t1l, NTOK, D, D, 0,
                                nullptr, nullptr);
    tc_gemm<<<gD, 256, GSMEM>>>(t1h, t1l, wth + OFF_A1, wtl + OFF_A1,
                                nullptr, nullptr, nullptr, t2h, t2l, NTOK, D, D, 0,
                                nullptr, nullptr);
    tc_gemm<<<gD, 256, GSMEM>>>(t2h, t2l, wth + OFF_A2, wtl + OFF_A2,
                                heavy_b, nullptr, x, nullptr, nullptr, NTOK, D, D, 2,
                                nullptr, nullptr);

    ln_kernel<<<NTOK / 8, 256>>>(x, norm_g, norm_b, h, nullptr, nullptr);
    mean_kernel<<<BB * 8, 256>>>(h, xm);
    cls_kernel<<<1, 128>>>(xm, cls_W, cls_b, (float*)d_out);
}

// round 16
// speedup vs baseline: 1.3303x; 1.3303x over previous
#include <cuda_runtime.h>
#include <cuda_bf16.h>
#include <cstdint>
#include <math.h>

#if defined(__CUDA_ARCH_FEAT_SM103_ALL) || defined(__CUDA_ARCH_FEAT_SM100_ALL)
#define HAS_TC 1
#else
#define HAS_TC 0
#endif

#define D    512
#define NH   8
#define HD   64
#define NL   4
#define FFD  2048
#define NCL  10
#define BB   8
#define TT   1024
#define NTOK (BB*TT)   // 8192

#define DDm (D*D)       // 262144
#define DFm (D*FFD)     // 1048576

// weight scratch offsets (elements), transposed [N,K] bf16 hi/lo
#define OFF_QKV 0
#define OFF_WO  (12*DDm)
#define OFF_W1  (16*DDm)
#define OFF_W2  (OFF_W1 + 4*DFm)
#define OFF_HW  (OFF_W2 + 4*DFm)
#define OFF_A1  (OFF_HW + DDm)
#define OFF_A2  (OFF_A1 + DDm)
#define WT_TOTAL (OFF_A2 + DDm)

// ---------------- scratch (device globals; no allocation) ----------------
__device__ __align__(16) float g_x [NTOK*D];
__device__ __align__(16) float g_h [NTOK*D];
__device__ __align__(16) __nv_bfloat16 g_hh  [NTOK*D],    g_hl  [NTOK*D];
__device__ __align__(16) __nv_bfloat16 g_qkvh[NTOK*3*D],  g_qkvl[NTOK*3*D];
__device__ __align__(16) __nv_bfloat16 g_vth [NTOK*D],    g_vtl [NTOK*D];
__device__ __align__(16) __nv_bfloat16 g_oh  [NTOK*D],    g_ol  [NTOK*D];
__device__ __align__(16) __nv_bfloat16 g_ffh [NTOK*FFD],  g_ffl [NTOK*FFD];
__device__ __align__(16) __nv_bfloat16 g_t1h [NTOK*D],    g_t1l [NTOK*D];
__device__ __align__(16) __nv_bfloat16 g_t2h [NTOK*D],    g_t2l [NTOK*D];
__device__ __align__(16) __nv_bfloat16 g_xh  [NTOK*D],    g_xl  [NTOK*D];
__device__ __align__(16) __nv_bfloat16 g_wth [WT_TOTAL],  g_wtl [WT_TOTAL];
__device__ __align__(16) float g_bcat[NL*3*D];
__device__ __align__(16) float g_xm[BB*D];

// ===================== PTX helpers (sm_103a) =====================
__device__ __forceinline__ uint32_t smem_u32(const void* p) {
    uint32_t a;
    asm("{ .reg .u64 t; cvta.to.shared.u64 t, %1; cvt.u32.u64 %0, t; }" : "=r"(a) : "l"(p));
    return a;
}
__device__ __forceinline__ uint32_t elect_one() {
    uint32_t p;
    asm volatile("{\n\t.reg .pred p;\n\telect.sync _|p, 0xFFFFFFFF;\n\tselp.b32 %0, 1, 0, p;\n\t}" : "=r"(p));
    return p;
}
#define TCGEN05_ALLOC(sa, n) \
    asm volatile("tcgen05.alloc.cta_group::1.sync.aligned.shared::cta.b32 [%0], %1;" \
                 :: "r"((uint32_t)(sa)), "r"((uint32_t)(n)) : "memory")
#define TCGEN05_DEALLOC(t, n) \
    asm volatile("tcgen05.dealloc.cta_group::1.sync.aligned.b32 %0, %1;" :: "r"(t), "r"((uint32_t)(n)))
#define TCGEN05_RELINQ() \
    asm volatile("tcgen05.relinquish_alloc_permit.cta_group::1.sync.aligned;")
#define TCGEN05_COMMIT(mb) \
    asm volatile("tcgen05.commit.cta_group::1.mbarrier::arrive::one.shared::cluster.b64 [%0];" \
                 :: "r"((uint32_t)(mb)) : "memory")
#define TCGEN05_FENCE_BEFORE() asm volatile("tcgen05.fence::before_thread_sync;" ::: "memory")
#define TCGEN05_FENCE_AFTER()  asm volatile("tcgen05.fence::after_thread_sync;" ::: "memory")
#define TCGEN05_WAIT_LD()      asm volatile("tcgen05.wait::ld.sync.aligned;" ::: "memory")
#define FENCE_ASYNC_SHARED()   asm volatile("fence.proxy.async.shared::cta;" ::: "memory")
#define MBARRIER_INIT(mb, c) \
    asm volatile("mbarrier.init.shared.b64 [%0], %1;" :: "r"((uint32_t)(mb)), "r"((uint32_t)(c)) : "memory")
#define MBARRIER_INVAL(mb) \
    asm volatile("mbarrier.inval.shared.b64 [%0];" :: "r"((uint32_t)(mb)) : "memory")
#define MBARRIER_WAIT_PARITY(mb, par) do { \
    uint32_t _m = (uint32_t)(mb), _p = (uint32_t)(par), _d; \
    asm volatile("{\n\t.reg .pred p;\n\t" \
        "mbarrier.try_wait.parity.acquire.cta.shared::cta.b64 p, [%1], %2;\n\t" \
        "selp.b32 %0, 1, 0, p;\n\t}" : "=r"(_d) : "r"(_m), "r"(_p) : "memory"); \
    if (!_d) { \
        asm volatile("{\n\t.reg .pred P1;\n\t" \
            "WL_%=:\n\t" \
            "mbarrier.try_wait.parity.acquire.cta.shared::cta.b64 P1, [%0], %1, 0x989680;\n\t" \
            "@P1 bra.uni WD_%=;\n\t" \
            "bra.uni WL_%=;\n\t" \
            "WD_%=:\n\t}" :: "r"(_m), "r"(_p) : "memory"); \
    } \
} while(0)
#define TCGEN05_LD_X32(r, ta) \
    asm volatile("tcgen05.ld.sync.aligned.32x32b.x32.b32 " \
        "{%0, %1, %2, %3, %4, %5, %6, %7, %8, %9, %10, %11, %12, %13, %14, %15, " \
        " %16, %17, %18, %19, %20, %21, %22, %23, %24, %25, %26, %27, %28, %29, %30, %31}, [%32];" \
        : "=r"((r)[0]),  "=r"((r)[1]),  "=r"((r)[2]),  "=r"((r)[3]), \
          "=r"((r)[4]),  "=r"((r)[5]),  "=r"((r)[6]),  "=r"((r)[7]), \
          "=r"((r)[8]),  "=r"((r)[9]),  "=r"((r)[10]), "=r"((r)[11]), \
          "=r"((r)[12]), "=r"((r)[13]), "=r"((r)[14]), "=r"((r)[15]), \
          "=r"((r)[16]), "=r"((r)[17]), "=r"((r)[18]), "=r"((r)[19]), \
          "=r"((r)[20]), "=r"((r)[21]), "=r"((r)[22]), "=r"((r)[23]), \
          "=r"((r)[24]), "=r"((r)[25]), "=r"((r)[26]), "=r"((r)[27]), \
          "=r"((r)[28]), "=r"((r)[29]), "=r"((r)[30]), "=r"((r)[31]) \
        : "r"(ta))
#define CP_ASYNC16(dst, src) \
    asm volatile("cp.async.cg.shared.global [%0], [%1], 16;" \
                 :: "r"((uint32_t)(dst)), "l"(src) : "memory")
#define CP_ASYNC_COMMIT() asm volatile("cp.async.commit_group;" ::: "memory")
#define CP_ASYNC_WAIT0()  asm volatile("cp.async.wait_group 0;" ::: "memory")

static constexpr uint64_t SMEM_DESC_BASE_SW128 =
    (uint64_t(2)  << 61) | (uint64_t(1) << 46) | (uint64_t(64) << 32) | (uint64_t(1) << 16);
#define MAKE_SMEM_DESC(a) (SMEM_DESC_BASE_SW128 | ((uint64_t)((a) >> 4) & 0x3FFF))

__device__ __forceinline__ void mma_bf16_ss(uint32_t d, uint64_t ad, uint64_t bd,
                                            uint32_t idesc, uint32_t en) {
#if HAS_TC
    uint32_t z = 0;
    asm volatile("{\n\t.reg .pred p;\n\tsetp.ne.u32 p, %5, 0;\n\t"
        "tcgen05.mma.cta_group::1.kind::f16 [%0], %1, %2, %3, {%4, %4, %4, %4}, p;\n\t}"
        :: "r"(d), "l"(ad), "l"(bd), "r"(idesc), "r"(z), "r"(en) : "memory");
#endif
}

// idesc: F32 accum, BF16 a/b; M=128 with N=128 / N=64
#define IDESC_128 ((1u<<4) | (1u<<7) | (1u<<10) | (16u<<17) | (8u<<24))
#define IDESC_64  ((1u<<4) | (1u<<7) | (1u<<10) | (8u<<17)  | (8u<<24))

#define EPS 132
#define SWZ(o) ((o) ^ (((o) >> 3) & 0x70))

// ---------------- embedding + pos enc + bias concat ------------------------
__global__ void embed_kernel(const int* __restrict__ tokens,
                             const float* __restrict__ emb,
                             float* __restrict__ x,
                             const float* __restrict__ bq, const float* __restrict__ bk,
                             const float* __restrict__ bv, float* __restrict__ bcat) {
    int i  = blockIdx.x * 256 + threadIdx.x;
    if (i < NL * 3 * D) {
        int l = i / (3 * D), c = i % (3 * D);
        int s = c >> 9, cc = c & 511;
        const float* src = (s == 0) ? bq : (s == 1) ? bk : bv;
        bcat[i] = src[l * D + cc];
    }
    int d  = i & (D - 1);
    int bt = i >> 9;
    int t  = bt & (TT - 1);
    int tok = tokens[bt];
    int kk = d >> 1;
    float freq = expf((float)(2 * kk) * (-0.0179889460f));
    float ang  = (float)t * freq;
    float pe   = (d & 1) ? cosf(ang) : sinf(ang);
    x[i] = emb[(size_t)tok * D + d] + pe;
}

// ---------------- layernorm ------------------------------------------------
__global__ __launch_bounds__(256) void ln_kernel(const float* __restrict__ x,
                                                 const float* __restrict__ g,
                                                 const float* __restrict__ b,
                                                 float* __restrict__ outf,
                                                 __nv_bfloat16* __restrict__ oh,
                                                 __nv_bfloat16* __restrict__ ol) {
    int warp = threadIdx.x >> 5, lane = threadIdx.x & 31;
    int row  = blockIdx.x * 8 + warp;
    const float* xr = x + (size_t)row * D;
    float v[16];
    float s = 0.f;
#pragma unroll
    for (int i = 0; i < 16; i++) { v[i] = xr[lane + i * 32]; s += v[i]; }
#pragma unroll
    for (int o = 16; o; o >>= 1) s += __shfl_xor_sync(0xffffffffu, s, o);
    float mean = s * (1.0f / D);
    float s2 = 0.f;
#pragma unroll
    for (int i = 0; i < 16; i++) { float dd = v[i] - mean; s2 += dd * dd; }
#pragma unroll
    for (int o = 16; o; o >>= 1) s2 += __shfl_xor_sync(0xffffffffu, s2, o);
    float rstd = rsqrtf(s2 * (1.0f / D) + 1e-5f);
#pragma unroll
    for (int i = 0; i < 16; i++) {
        int c = lane + i * 32;
        float y = (v[i] - mean) * rstd * g[c] + b[c];
        size_t idx = (size_t)row * D + c;
        if (outf) outf[idx] = y;
        else {
            __nv_bfloat16 hv = __float2bfloat16_rn(y);
            oh[idx] = hv;
            ol[idx] = __float2bfloat16_rn(y - __bfloat162float(hv));
        }
    }
}

// ---------------- fp32 -> split bf16 (elementwise, no transpose) -----------
__global__ void split_kernel(const float* __restrict__ in,
                             __nv_bfloat16* __restrict__ hi,
                             __nv_bfloat16* __restrict__ lo) {
    int i = blockIdx.x * 256 + threadIdx.x;
    float v = in[i];
    __nv_bfloat16 hv = __float2bfloat16_rn(v);
    hi[i] = hv;
    lo[i] = __float2bfloat16_rn(v - __bfloat162float(hv));
}

// ---------------- generic weight transpose+split body ----------------------
__device__ __forceinline__ void wsplit_body(const float* W, __nv_bfloat16* th,
                                            __nv_bfloat16* tl, int K, int N,
                                            int k0, int n0, float tbuf[32][33]) {
    int x = threadIdx.x, y = threadIdx.y;
#pragma unroll
    for (int j = 0; j < 32; j += 8)
        tbuf[y + j][x] = W[(size_t)(k0 + y + j) * N + n0 + x];
    __syncthreads();
#pragma unroll
    for (int j = 0; j < 32; j += 8) {
        float v = tbuf[x][y + j];
        __nv_bfloat16 hv = __float2bfloat16_rn(v);
        size_t o = (size_t)(n0 + y + j) * K + k0 + x;
        th[o] = hv;
        tl[o] = __float2bfloat16_rn(v - __bfloat162float(hv));
    }
}

__global__ void wsplit_kernel(const float* __restrict__ W,
                              __nv_bfloat16* __restrict__ th,
                              __nv_bfloat16* __restrict__ tl,
                              int K, int N) {
    __shared__ float t[32][33];
    size_t mo = (size_t)blockIdx.z * K * N;
    wsplit_body(W + mo, th + mo, tl + mo, K, N,
                blockIdx.y * 32, blockIdx.x * 32, t);
}

__global__ void wsplit_qkvoh(const float* __restrict__ Wq, const float* __restrict__ Wk,
                             const float* __restrict__ Wv, const float* __restrict__ Wo,
                             const float* __restrict__ hw, const float* __restrict__ a1,
                             const float* __restrict__ a2,
                             __nv_bfloat16* __restrict__ th, __nv_bfloat16* __restrict__ tl) {
    __shared__ float t[32][33];
    int z = blockIdx.z;
    const float* src;
    size_t dst;
    if (z < 16) {
        int s = z >> 2, l = z & 3;
        src = ((s == 0) ? Wq : (s == 1) ? Wk : (s == 2) ? Wv : Wo) + (size_t)l * DDm;
        dst = (s < 3) ? (size_t)OFF_QKV + (size_t)l * 3 * DDm + (size_t)s * DDm
                      : (size_t)OFF_WO + (size_t)l * DDm;
    } else {
        int s = z - 16;
        src = (s == 0) ? hw : (s == 1) ? a1 : a2;
        dst = (size_t)OFF_HW + (size_t)s * DDm;
    }
    wsplit_body(src, th + dst, tl + dst, D, D, blockIdx.y * 32, blockIdx.x * 32, t);
}

// ---------------- tcgen05 split-bf16 GEMM (2 CTAs/SM, round-14) ------------
#define GSMEM (1024 + 65536)
__global__ __launch_bounds__(256, 2) __cluster_dims__(1, 1, 1)
void tc_gemm(const __nv_bfloat16* __restrict__ Ahi, const __nv_bfloat16* __restrict__ Alo,
             const __nv_bfloat16* __restrict__ Bhi, const __nv_bfloat16* __restrict__ Blo,
             const float* __restrict__ bias, const float* __restrict__ res,
             float* __restrict__ Cf,
             __nv_bfloat16* __restrict__ Ch, __nv_bfloat16* __restrict__ Cl,
             int M, int N, int K, int act,
             __nv_bfloat16* __restrict__ Vth, __nv_bfloat16* __restrict__ Vtl) {
#if HAS_TC
    extern __shared__ char smem[];
    uint32_t sb = smem_u32(smem);
    int tid = threadIdx.x, wid = tid >> 5, lane = tid & 31;
    int bm = blockIdx.y * 128, bn = blockIdx.x * 128;

    if (wid == 0) { TCGEN05_ALLOC(sb, 128); TCGEN05_RELINQ(); }
    if (tid == 0) { MBARRIER_INIT(sb + 16, 1); }
    __syncthreads();
    uint32_t tmem;
    asm volatile("ld.shared.b32 %0, [%1];" : "=r"(tmem) : "r"(sb));

    int nchunk = K >> 6;
    int ph = 0;

    for (int c = 0; c < nchunk; c++) {
        if (c > 0) { MBARRIER_WAIT_PARITY(sb + 16, ph); ph ^= 1; }
#pragma unroll
        for (int t = 0; t < 4; t++) {
            const __nv_bfloat16* src = (t == 0) ? Ahi : (t == 1) ? Alo : (t == 2) ? Bhi : Blo;
            int rb = (t < 2) ? bm : bn;
            uint32_t tb = sb + 1024u + t * 16384u;
#pragma unroll
            for (int i = 0; i < 4; i++) {
                int e = tid + i * 256;
                int r = e >> 3, cq = e & 7;
                uint32_t off = (uint32_t)(r * 128 + cq * 16);
                CP_ASYNC16(tb + SWZ(off), src + (size_t)(rb + r) * K + c * 64 + cq * 8);
            }
        }
        CP_ASYNC_COMMIT();
        CP_ASYNC_WAIT0();
        FENCE_ASYNC_SHARED();
        __syncthreads();
        if (wid == 0) {
            if (elect_one()) {
                uint64_t aH = MAKE_SMEM_DESC(sb + 1024u);
                uint64_t aL = MAKE_SMEM_DESC(sb + 1024u + 16384u);
                uint64_t bH = MAKE_SMEM_DESC(sb + 1024u + 32768u);
                uint64_t bL = MAKE_SMEM_DESC(sb + 1024u + 49152u);
#pragma unroll
                for (int s = 0; s < 4; s++)
                    mma_bf16_ss(tmem, aH + 2 * s, bH + 2 * s, IDESC_128, (c != 0 || s != 0));
#pragma unroll
                for (int s = 0; s < 4; s++)
                    mma_bf16_ss(tmem, aH + 2 * s, bL + 2 * s, IDESC_128, 1u);
#pragma unroll
                for (int s = 0; s < 4; s++)
                    mma_bf16_ss(tmem, aL + 2 * s, bH + 2 * s, IDESC_128, 1u);
                TCGEN05_COMMIT(sb + 16);
            }
        }
    }
    MBARRIER_WAIT_PARITY(sb + 16, ph); ph ^= 1;
    TCGEN05_FENCE_AFTER();

    int w4 = wid & 3;
    int cb = (wid >> 2) * 64;
    uint32_t dr[64];
    TCGEN05_LD_X32(dr,      tmem + cb);
    TCGEN05_LD_X32(dr + 32, tmem + cb + 32);
    TCGEN05_WAIT_LD();
    TCGEN05_FENCE_BEFORE();
    float* so = (float*)(smem + 1024);
    bool dovt = (Vth != nullptr) && (bn >= 1024);
    int b  = bm >> 10;
    int t0 = bm & 1023;
    int vb = bn - 1024;
#pragma unroll
    for (int p = 0; p < 2; p++) {
        __syncthreads();
        if ((w4 >> 1) == p) {
            int rloc = (w4 & 1) * 32 + lane;
#pragma unroll
            for (int j = 0; j < 64; j++) so[rloc * EPS + cb + j] = __uint_as_float(dr[j]);
        }
        __syncthreads();
#pragma unroll
        for (int i = 0; i < 8; i++) {
            int e = tid + i * 256;
            int rl = e >> 5, c4 = (e & 31) << 2;
            float4 v = *(float4*)&so[rl * EPS + c4];
            float* vv = (float*)&v;
            int row = bm + p * 64 + rl;
            if (bias) {
                float4 bv = *(const float4*)&bias[bn + c4];
                vv[0] += bv.x; vv[1] += bv.y; vv[2] += bv.z; vv[3] += bv.w;
            }
            if (act == 1) {
#pragma unroll
                for (int q = 0; q < 4; q++)
                    vv[q] = 0.5f * vv[q] * (1.0f + erff(vv[q] * 0.70710678f));
            } else if (act == 2) {
#pragma unroll
                for (int q = 0; q < 4; q++) vv[q] = tanhf(vv[q]);
            }
            if (res) {
                float4 rv = *(const float4*)&res[(size_t)row * N + bn + c4];
                vv[0] += rv.x; vv[1] += rv.y; vv[2] += rv.z; vv[3] += rv.w;
            }
            size_t gidx = (size_t)row * N + bn + c4;
            if (Cf) *(float4*)&Cf[gidx] = v;
            if (Ch) {
                __nv_bfloat16 h0 = __float2bfloat16_rn(vv[0]);
                __nv_bfloat16 h1 = __float2bfloat16_rn(vv[1]);
                __nv_bfloat16 h2 = __float2bfloat16_rn(vv[2]);
                __nv_bfloat16 h3 = __float2bfloat16_rn(vv[3]);
                __nv_bfloat162 hp0(h0, h1), hp1(h2, h3);
                __nv_bfloat162 lp0(__float2bfloat16_rn(vv[0] - __bfloat162float(h0)),
                                   __float2bfloat16_rn(vv[1] - __bfloat162float(h1)));
                __nv_bfloat162 lp1(__float2bfloat16_rn(vv[2] - __bfloat162float(h2)),
                                   __float2bfloat16_rn(vv[3] - __bfloat162float(h3)));
                *(uint2*)&Ch[gidx] = make_uint2(*(uint32_t*)&hp0, *(uint32_t*)&hp1);
                *(uint2*)&Cl[gidx] = make_uint2(*(uint32_t*)&lp0, *(uint32_t*)&lp1);
            }
            if (dovt) *(float4*)&so[rl * EPS + c4] = v;
        }
        if (dovt) {
            __syncthreads();
#pragma unroll
            for (int i = 0; i < 8; i++) {
                int e = tid + i * 256;
                int cl = e >> 4, tg = (e & 15) << 2;
                float f0 = so[(tg + 0) * EPS + cl];
                float f1 = so[(tg + 1) * EPS + cl];
                float f2 = so[(tg + 2) * EPS + cl];
                float f3 = so[(tg + 3) * EPS + cl];
                __nv_bfloat16 h0 = __float2bfloat16_rn(f0);
                __nv_bfloat16 h1 = __float2bfloat16_rn(f1);
                __nv_bfloat16 h2 = __float2bfloat16_rn(f2);
                __nv_bfloat16 h3 = __float2bfloat16_rn(f3);
                __nv_bfloat162 hp0(h0, h1), hp1(h2, h3);
                __nv_bfloat162 lp0(__float2bfloat16_rn(f0 - __bfloat162float(h0)),
                                   __float2bfloat16_rn(f1 - __bfloat162float(h1)));
                __nv_bfloat162 lp1(__float2bfloat16_rn(f2 - __bfloat162float(h2)),
                                   __float2bfloat16_rn(f3 - __bfloat162float(h3)));
                size_t g = ((size_t)(b * 512 + vb + cl)) * 1024 + t0 + p * 64 + tg;
                *(uint2*)&Vth[g] = make_uint2(*(uint32_t*)&hp0, *(uint32_t*)&hp1);
                *(uint2*)&Vtl[g] = make_uint2(*(uint32_t*)&lp0, *(uint32_t*)&lp1);
            }
        }
    }
    __syncthreads();
    if (tid == 0) MBARRIER_INVAL(sb + 16);
    __syncthreads();
    if (wid == 0) TCGEN05_DEALLOC(tmem, 128);
#else
    // compile-only fallback for non-'a' PTX pass (never selected on GB300)
    extern __shared__ char smem[];
    float* As = (float*)smem;
    float* Bs = (float*)(smem + 4096);
    int tid = threadIdx.x;
    int bm = blockIdx.y * 128, bn = blockIdx.x * 128;
    int tx = tid & 15, ty = tid >> 4;
    int lr = tid >> 1, lk = (tid & 1) * 4;
    float acc[8][8];
#pragma unroll
    for (int i = 0; i < 8; i++)
#pragma unroll
        for (int j = 0; j < 8; j++) acc[i][j] = 0.f;
    for (int k0 = 0; k0 < K; k0 += 8) {
        float av[4], bv[4];
#pragma unroll
        for (int i = 0; i < 4; i++) {
            size_t ai = (size_t)(bm + lr) * K + k0 + lk + i;
            av[i] = __bfloat162float(Ahi[ai]) + __bfloat162float(Alo[ai]);
            size_t bi = (size_t)(bn + lr) * K + k0 + lk + i;
            bv[i] = __bfloat162float(Bhi[bi]) + __bfloat162float(Blo[bi]);
        }
        __syncthreads();
#pragma unroll
        for (int i = 0; i < 4; i++) {
            As[(lk + i) * 128 + lr] = av[i];
            Bs[(lk + i) * 128 + lr] = bv[i];
        }
        __syncthreads();
#pragma unroll
        for (int kk = 0; kk < 8; kk++) {
            float ar8[8], br8[8];
#pragma unroll
            for (int i = 0; i < 8; i++) { ar8[i] = As[kk * 128 + ty * 8 + i]; br8[i] = Bs[kk * 128 + tx * 8 + i]; }
#pragma unroll
            for (int i = 0; i < 8; i++)
#pragma unroll
                for (int j = 0; j < 8; j++) acc[i][j] += ar8[i] * br8[j];
        }
    }
#pragma unroll
    for (int i = 0; i < 8; i++) {
        int row = bm + ty * 8 + i;
#pragma unroll
        for (int j = 0; j < 8; j++) {
            int col = bn + tx * 8 + j;
            float v = acc[i][j];
            if (bias) v += bias[col];
            if (act == 1) v = 0.5f * v * (1.0f + erff(v * 0.70710678f));
            else if (act == 2) v = tanhf(v);
            if (res) v += res[(size_t)row * N + col];
            if (Cf) Cf[(size_t)row * N + col] = v;
            if (Ch) {
                __nv_bfloat16 hv = __float2bfloat16_rn(v);
                Ch[(size_t)row * N + col] = hv;
                Cl[(size_t)row * N + col] = __float2bfloat16_rn(v - __bfloat162float(hv));
            }
            if (Vth && bn >= 1024) {
                int b = row >> 10, t = row & 1023;
                size_t g = ((size_t)(b * 512 + (bn - 1024) + tx * 8 + j)) * 1024 + t;
                __nv_bfloat16 hv = __float2bfloat16_rn(v);
                Vth[g] = hv;
                Vtl[g] = __float2bfloat16_rn(v - __bfloat162float(hv));
            }
        }
    }
#endif
}

// ---------------- tcgen05 attention (round-14 version: 128-key, occ 1) -----
#define ATT_QH 1024
#define ATT_QL (ATT_QH+16384)
#define ATT_K  (ATT_QL+16384)          // 2 bufs x (KH 16K + KL 16K) = 64K
#define ATT_VH (ATT_K+65536)
#define ATT_VL (ATT_VH+16384)
#define ATT_PH (ATT_VL+16384)
#define ATT_PL (ATT_PH+32768)
#define ATT_LS (ATT_PL+32768)
#define ATT_SMEM (ATT_LS+2048)

__global__ __launch_bounds__(256, 1) __cluster_dims__(1, 1, 1)
void tc_attn(const __nv_bfloat16* __restrict__ qkvh, const __nv_bfloat16* __restrict__ qkvl,
             const __nv_bfloat16* __restrict__ vth, const __nv_bfloat16* __restrict__ vtl,
             __nv_bfloat16* __restrict__ Oh, __nv_bfloat16* __restrict__ Ol) {
#if HAS_TC
    extern __shared__ char smem[];
    uint32_t sb = smem_u32(smem);
    int tid = threadIdx.x, wid = tid >> 5, lane = tid & 31;
    int bh = blockIdx.x, b = bh >> 3, h = bh & 7;
    int q0 = blockIdx.y * 128;
    int w4 = wid & 3, half = wid >> 2, cb = half * 64;
    int srow = w4 * 32 + lane;

    if (wid == 0) { TCGEN05_ALLOC(sb, 256); TCGEN05_RELINQ(); }
    if (tid == 0) { MBARRIER_INIT(sb + 16, 1); }
    __syncthreads();
    uint32_t tmem;
    asm volatile("ld.shared.b32 %0, [%1];" : "=r"(tmem) : "r"(sb));

    const __nv_bfloat16* Qh = qkvh + (size_t)(b * TT + q0) * 1536 + h * 64;
    const __nv_bfloat16* Ql = qkvl + (size_t)(b * TT + q0) * 1536 + h * 64;
    const __nv_bfloat16* Kh = qkvh + (size_t)(b * TT) * 1536 + 512 + h * 64;
    const __nv_bfloat16* Kl = qkvl + (size_t)(b * TT) * 1536 + 512 + h * 64;
    const __nv_bfloat16* Vh = vth + (size_t)bh * 64 * TT;
    const __nv_bfloat16* Vl = vtl + (size_t)bh * 64 * TT;

    // preload Q + K(0)
#pragma unroll
    for (int i = 0; i < 4; i++) {
        int e = tid + i * 256;
        int r = e >> 3, u = e & 7;
        uint32_t off = SWZ((uint32_t)(r * 128 + u * 16));
        CP_ASYNC16(sb + ATT_QH + off, Qh + (size_t)r * 1536 + u * 8);
        CP_ASYNC16(sb + ATT_QL + off, Ql + (size_t)r * 1536 + u * 8);
        CP_ASYNC16(sb + ATT_K + off,          Kh + (size_t)r * 1536 + u * 8);
        CP_ASYNC16(sb + ATT_K + 16384u + off, Kl + (size_t)r * 1536 + u * 8);
    }
    CP_ASYNC_COMMIT();

    float lacc = 0.f;
    int ph = 0;

    for (int kt = 0; kt < 8; kt++) {
        if (kt > 0) { MBARRIER_WAIT_PARITY(sb + 16, ph); ph ^= 1; }
#pragma unroll
        for (int i = 0; i < 4; i++) {
            int e = tid + i * 256;
            int r = e >> 4, u = e & 15;
            int ch = u >> 3, u2 = u & 7;
            uint32_t off = SWZ((uint32_t)(r * 128 + u2 * 16));
            CP_ASYNC16(sb + ATT_VH + ch * 8192 + off, Vh + (size_t)r * TT + kt * 128 + u * 8);
            CP_ASYNC16(sb + ATT_VL + ch * 8192 + off, Vl + (size_t)r * TT + kt * 128 + u * 8);
        }
        CP_ASYNC_COMMIT();
        CP_ASYNC_WAIT0();
        FENCE_ASYNC_SHARED();
        __syncthreads();
        uint32_t kb = sb + ATT_K + (uint32_t)(kt & 1) * 32768u;
        if (wid == 0 && elect_one()) {
            uint64_t qH = MAKE_SMEM_DESC(sb + ATT_QH), qL = MAKE_SMEM_DESC(sb + ATT_QL);
            uint64_t kH = MAKE_SMEM_DESC(kb), kL = MAKE_SMEM_DESC(kb + 16384u);
#pragma unroll
            for (int s = 0; s < 4; s++) mma_bf16_ss(tmem, qH + 2 * s, kH + 2 * s, IDESC_128, s != 0);
#pragma unroll
            for (int s = 0; s < 4; s++) mma_bf16_ss(tmem, qH + 2 * s, kL + 2 * s, IDESC_128, 1u);
#pragma unroll
            for (int s = 0; s < 4; s++) mma_bf16_ss(tmem, qL + 2 * s, kH + 2 * s, IDESC_128, 1u);
            TCGEN05_COMMIT(sb + 16);
        }
        MBARRIER_WAIT_PARITY(sb + 16, ph); ph ^= 1;
        if (kt < 7) {
            uint32_t kb2 = sb + ATT_K + (uint32_t)((kt + 1) & 1) * 32768u;
#pragma unroll
            for (int i = 0; i < 4; i++) {
                int e = tid + i * 256;
                int r = e >> 3, u = e & 7;
                uint32_t off = SWZ((uint32_t)(r * 128 + u * 16));
                CP_ASYNC16(kb2 + off,          Kh + (size_t)((kt + 1) * 128 + r) * 1536 + u * 8);
                CP_ASYNC16(kb2 + 16384u + off, Kl + (size_t)((kt + 1) * 128 + r) * 1536 + u * 8);
            }
            CP_ASYNC_COMMIT();
        }
        TCGEN05_FENCE_AFTER();
        uint32_t dr[64];
        TCGEN05_LD_X32(dr,      tmem + cb);
        TCGEN05_LD_X32(dr + 32, tmem + cb + 32);
        TCGEN05_WAIT_LD();
#pragma unroll
        for (int j = 0; j < 64; j += 2) {
            float p0 = __expf(__uint_as_float(dr[j])     * 0.125f);
            float p1 = __expf(__uint_as_float(dr[j + 1]) * 0.125f);
            lacc += p0 + p1;
            __nv_bfloat16 h0 = __float2bfloat16_rn(p0), h1 = __float2bfloat16_rn(p1);
            __nv_bfloat162 hp(h0, h1);
            __nv_bfloat162 lp(__float2bfloat16_rn(p0 - __bfloat162float(h0)),
                              __float2bfloat16_rn(p1 - __bfloat162float(h1)));
            uint32_t off = SWZ((uint32_t)(srow * 128 + j * 2));
            *(uint32_t*)(smem + ATT_PH + half * 16384 + off) = *(uint32_t*)&hp;
            *(uint32_t*)(smem + ATT_PL + half * 16384 + off) = *(uint32_t*)&lp;
        }
        TCGEN05_FENCE_BEFORE();
        FENCE_ASYNC_SHARED();
        __syncthreads();
        if (wid == 0 && elect_one()) {
#pragma unroll
            for (int ch = 0; ch < 2; ch++) {
                uint64_t pH = MAKE_SMEM_DESC(sb + ATT_PH + ch * 16384);
                uint64_t pL = MAKE_SMEM_DESC(sb + ATT_PL + ch * 16384);
                uint64_t vH = MAKE_SMEM_DESC(sb + ATT_VH + ch * 8192);
                uint64_t vL = MAKE_SMEM_DESC(sb + ATT_VL + ch * 8192);
#pragma unroll
                for (int s = 0; s < 4; s++)
                    mma_bf16_ss(tmem + 128, pH + 2 * s, vH + 2 * s, IDESC_64,
                                !(kt == 0 && ch == 0 && s == 0));
#pragma unroll
                for (int s = 0; s < 4; s++)
                    mma_bf16_ss(tmem + 128, pH + 2 * s, vL + 2 * s, IDESC_64, 1u);
#pragma unroll
                for (int s = 0; s < 4; s++)
                    mma_bf16_ss(tmem + 128, pL + 2 * s, vH + 2 * s, IDESC_64, 1u);
            }
            TCGEN05_COMMIT(sb + 16);
        }
    }
    MBARRIER_WAIT_PARITY(sb + 16, ph); ph ^= 1;
    TCGEN05_FENCE_AFTER();

    *(float*)(smem + ATT_LS + (half * 128 + srow) * 4) = lacc;
    __syncthreads();
    if (wid < 4) {
        float lt = *(float*)(smem + ATT_LS + srow * 4) +
                   *(float*)(smem + ATT_LS + (128 + srow) * 4);
        float invl = 1.0f / lt;
        uint32_t orv[64];
        TCGEN05_LD_X32(orv,      tmem + 128);
        TCGEN05_LD_X32(orv + 32, tmem + 160);
        TCGEN05_WAIT_LD();
        TCGEN05_FENCE_BEFORE();
#pragma unroll
        for (int j = 0; j < 64; j += 2) {
            float o0 = __uint_as_float(orv[j]) * invl;
            float o1 = __uint_as_float(orv[j + 1]) * invl;
            __nv_bfloat16 h0 = __float2bfloat16_rn(o0), h1 = __float2bfloat16_rn(o1);
            __nv_bfloat162 hp(h0, h1);
            __nv_bfloat162 lp(__float2bfloat16_rn(o0 - __bfloat162float(h0)),
                              __float2bfloat16_rn(o1 - __bfloat162float(h1)));
            uint32_t off = SWZ((uint32_t)(srow * 128 + j * 2));
            *(uint32_t*)(smem + ATT_PH + off) = *(uint32_t*)&hp;
            *(uint32_t*)(smem + ATT_PL + off) = *(uint32_t*)&lp;
        }
    }
    __syncthreads();
#pragma unroll
    for (int i = 0; i < 4; i++) {
        int e = tid + i * 256;
        int r = e >> 3, u = e & 7;
        uint32_t off = SWZ((uint32_t)(r * 128 + u * 16));
        size_t g = (size_t)(b * TT + q0 + r) * D + h * 64 + u * 8;
        *(uint4*)(Oh + g) = *(uint4*)(smem + ATT_PH + off);
        *(uint4*)(Ol + g) = *(uint4*)(smem + ATT_PL + off);
    }
    __syncthreads();
    if (tid == 0) MBARRIER_INVAL(sb + 16);
    __syncthreads();
    if (wid == 0) TCGEN05_DEALLOC(tmem, 256);
#endif
}

// ---------------- mean over T (64 blocks, tree reduce) ---------------------
__global__ __launch_bounds__(256) void mean_kernel(const float* __restrict__ x,
                                                   float* __restrict__ out) {
    __shared__ float red[256];
    int b = blockIdx.x >> 3;
    int base = (blockIdx.x & 7) * 64;
    int dc = threadIdx.x & 63, tq = threadIdx.x >> 6;
    float s = 0.f;
    for (int t = tq; t < TT; t += 4)
        s += x[((size_t)(b * TT + t)) * D + base + dc];
    red[threadIdx.x] = s;
    __syncthreads();
    if (threadIdx.x < 64) {
        float tot = red[dc] + red[64 + dc] + red[128 + dc] + red[192 + dc];
        out[b * D + base + dc] = tot * (1.0f / TT);
    }
}

// ---------------- classifier ----------------------------------------------
__global__ void cls_kernel(const float* __restrict__ xm, const float* __restrict__ W,
                           const float* __restrict__ bias, float* __restrict__ out) {
    int i = threadIdx.x;
    if (i < BB * NCL) {
        int b = i / NCL, c = i % NCL;
        float s = bias[c];
        for (int d = 0; d < D; d++) s += xm[b * D + d] * W[d * NCL + c];
        out[i] = s;
    }
}

// ---------------- launch ---------------------------------------------------
extern "C" void kernel_launch(void* const* d_in, const int* in_sizes, int n_in,
                              void* d_out, int out_size) {
    const int*   tokens = (const int*)  d_in[0];
    const float* emb    = (const float*)d_in[1];
    const float* Wq = (const float*)d_in[2],  *bq = (const float*)d_in[3];
    const float* Wk = (const float*)d_in[4],  *bk = (const float*)d_in[5];
    const float* Wv = (const float*)d_in[6],  *bv = (const float*)d_in[7];
    const float* Wo = (const float*)d_in[8],  *bo = (const float*)d_in[9];
    const float* ln1g = (const float*)d_in[10], *ln1b = (const float*)d_in[11];
    const float* ln2g = (const float*)d_in[12], *ln2b = (const float*)d_in[13];
    const float* W1 = (const float*)d_in[14], *b1 = (const float*)d_in[15];
    const float* W2 = (const float*)d_in[16], *b2 = (const float*)d_in[17];
    const float* heavy_w  = (const float*)d_in[18];
    const float* heavy_b  = (const float*)d_in[19];
    const float* heavy_a1 = (const float*)d_in[20];
    const float* heavy_a2 = (const float*)d_in[21];
    const float* norm_g = (const float*)d_in[22], *norm_b = (const float*)d_in[23];
    const float* cls_W  = (const float*)d_in[24], *cls_b  = (const float*)d_in[25];

    float *x, *h, *xm, *bcat;
    __nv_bfloat16 *hh, *hl, *qkvh, *qkvl, *vth, *vtl, *oh, *ol,
                  *ffh, *ffl, *t1h, *t1l, *t2h, *t2l, *xh, *xl, *wth, *wtl;
    cudaGetSymbolAddress((void**)&x,    g_x);
    cudaGetSymbolAddress((void**)&h,    g_h);
    cudaGetSymbolAddress((void**)&hh,   g_hh);   cudaGetSymbolAddress((void**)&hl,   g_hl);
    cudaGetSymbolAddress((void**)&qkvh, g_qkvh); cudaGetSymbolAddress((void**)&qkvl, g_qkvl);
    cudaGetSymbolAddress((void**)&vth,  g_vth);  cudaGetSymbolAddress((void**)&vtl,  g_vtl);
    cudaGetSymbolAddress((void**)&oh,   g_oh);   cudaGetSymbolAddress((void**)&ol,   g_ol);
    cudaGetSymbolAddress((void**)&ffh,  g_ffh);  cudaGetSymbolAddress((void**)&ffl,  g_ffl);
    cudaGetSymbolAddress((void**)&t1h,  g_t1h);  cudaGetSymbolAddress((void**)&t1l,  g_t1l);
    cudaGetSymbolAddress((void**)&t2h,  g_t2h);  cudaGetSymbolAddress((void**)&t2l,  g_t2l);
    cudaGetSymbolAddress((void**)&xh,   g_xh);   cudaGetSymbolAddress((void**)&xl,   g_xl);
    cudaGetSymbolAddress((void**)&wth,  g_wth);  cudaGetSymbolAddress((void**)&wtl,  g_wtl);
    cudaGetSymbolAddress((void**)&bcat, g_bcat);
    cudaGetSymbolAddress((void**)&xm,   g_xm);

    cudaFuncSetAttribute(tc_gemm, cudaFuncAttributeMaxDynamicSharedMemorySize, GSMEM);
    cudaFuncSetAttribute(tc_attn, cudaFuncAttributeMaxDynamicSharedMemorySize, ATT_SMEM);

    embed_kernel<<<NTOK * D / 256, 256>>>(tokens, emb, x, bq, bk, bv, bcat);
    wsplit_kernel<<<dim3(FFD/32, D/32,   NL), dim3(32,8)>>>(W1, wth + OFF_W1, wtl + OFF_W1, D, FFD);
    wsplit_kernel<<<dim3(D/32,   FFD/32, NL), dim3(32,8)>>>(W2, wth + OFF_W2, wtl + OFF_W2, FFD, D);
    wsplit_qkvoh<<<dim3(D/32, D/32, 19), dim3(32,8)>>>(Wq, Wk, Wv, Wo,
                                                       heavy_w, heavy_a1, heavy_a2, wth, wtl);

    dim3 gD(D / 128,     NTOK / 128);   // N=512
    dim3 gQ(3*D / 128,   NTOK / 128);   // N=1536 fused QKV
    dim3 gF(FFD / 128,   NTOK / 128);   // N=2048
    dim3 gC(D / 128,     D / 128);      // 512x512 combo GEMMs

    // ---- heavy-chain folding: comboT = (hw @ a1 @ a2)^T, precomputed ------
    // plain elementwise splits of a1 (into t1h/t1l) and hw (into oh/ol; both
    // buffers are free until the layer loop reuses them)
    split_kernel<<<DDm / 256, 256>>>(heavy_a1, t1h, t1l);
    split_kernel<<<DDm / 256, 256>>>(heavy_w,  oh,  ol);
    // U = a2^T @ a1^T = (a1 @ a2)^T   [A = a2^T split at OFF_A2, B = a1 plain]
    tc_gemm<<<gC, 256, GSMEM>>>(wth + OFF_A2, wtl + OFF_A2, t1h, t1l,
                                nullptr, nullptr, nullptr, t2h, t2l, D, D, D, 0,
                                nullptr, nullptr);
    // comboT = U @ hw^T = (hw @ a1 @ a2)^T   [B = hw plain]
    tc_gemm<<<gC, 256, GSMEM>>>(t2h, t2l, oh, ol,
                                nullptr, nullptr, nullptr, t1h, t1l, D, D, D, 0,
                                nullptr, nullptr);

    for (int l = 0; l < NL; l++) {
        ln_kernel<<<NTOK / 8, 256>>>(x, ln1g + l * D, ln1b + l * D, nullptr, hh, hl);
        tc_gemm<<<gQ, 256, GSMEM>>>(hh, hl,
                                    wth + OFF_QKV + (size_t)l * 3 * DDm,
                                    wtl + OFF_QKV + (size_t)l * 3 * DDm,
                                    bcat + l * 3 * D, nullptr,
                                    nullptr, qkvh, qkvl, NTOK, 3 * D, D, 0,
                                    vth, vtl);
        tc_attn<<<dim3(BB * NH, TT / 128), 256, ATT_SMEM>>>(qkvh, qkvl, vth, vtl, oh, ol);
        tc_gemm<<<gD, 256, GSMEM>>>(oh, ol,
                                    wth + OFF_WO + (size_t)l * DDm,
                                    wtl + OFF_WO + (size_t)l * DDm,
                                    bo + l * D, x, x, nullptr, nullptr, NTOK, D, D, 0,
                                    nullptr, nullptr);
        ln_kernel<<<NTOK / 8, 256>>>(x, ln2g + l * D, ln2b + l * D, nullptr, hh, hl);
        tc_gemm<<<gF, 256, GSMEM>>>(hh, hl,
                                    wth + OFF_W1 + (size_t)l * DFm,
                                    wtl + OFF_W1 + (size_t)l * DFm,
                                    b1 + l * FFD, nullptr, nullptr, ffh, ffl, NTOK, FFD, D, 1,
                                    nullptr, nullptr);
        tc_gemm<<<gD, 256, GSMEM>>>(ffh, ffl,
                                    wth + OFF_W2 + (size_t)l * DFm,
                                    wtl + OFF_W2 + (size_t)l * DFm,
                                    b2 + l * D, x, x,
                                    (l == NL - 1) ? xh : nullptr,
                                    (l == NL - 1) ? xl : nullptr,
                                    NTOK, D, FFD, 0, nullptr, nullptr);
    }

    // heavy layer: single GEMM against precomputed comboT, bias + tanh fused
    tc_gemm<<<gD, 256, GSMEM>>>(xh, xl, t1h, t1l,
                                heavy_b, nullptr, x, nullptr, nullptr, NTOK, D, D, 2,
                                nullptr, nullptr);

    ln_kernel<<<NTOK / 8, 256>>>(x, norm_g, norm_b, h, nullptr, nullptr);
    mean_kernel<<<BB * 8, 256>>>(h, xm);
    cls_kernel<<<1, 128>>>(xm, cls_W, cls_b, (float*)d_out);
}